// round 16
// baseline (speedup 1.0000x reference)
#include <cuda_runtime.h>
#include <cuda_fp16.h>
#include <cstdint>

// KMeans labels, two-pass:
//  PASS 1 (persistent): hh-only fp16 MMA screen with PACKED-KEY top-2:
//    key = (bits(score+512) & ~511) | idx  (order-preserving uint32, idx in
//    low 9 bits). Top-2 via pure IMNMX (umin/umax) - no predicate chains.
//    Gap > deterministic margin (fp16 trunc + key mask error) -> exact;
//    else rescue list.
//  PASS 2: exact 3-term (hh+hl+lh) fp16-split MMA rescore of listed points.

#define DIM      64
#define KCENT    512
#define TILE_M   256
#define CHN      128
#define NCH      4
#define THREADS  512
#define GRID1    148
#define P2GRID   148

// ---- pass1 smem ----
#define P1_SA   0u        // ah: 256 rows * 128B
#define P1_SB   32768u    // bh: 64 KB
#define P1_SC2  98304u    // 512 f32
#define P1_SXN  100352u   // 2 par * 512 f32
#define P1_RK1  104448u   // 2*256 u32 (m1 keys)
#define P1_RK2  106496u   // 2*256 u32 (m2 keys)
#define P1_SMEM 108544u

// ---- pass2 smem ----
#define P2_SA   0u
#define P2_SB   65536u
#define P2_SC2  196608u
#define P2_RV   198656u
#define P2_RI   200704u
#define P2_SMEM 202752u

__device__ __align__(16) __half g_bh[KCENT][DIM];   // rn16(-2c)
__device__ __align__(16) __half g_bl[KCENT][DIM];   // rn16(-2c - h)
__device__ __align__(16) float  g_c2[KCENT];
__device__ float g_maxn;
__device__ int   g_cnt;
__device__ int   g_list[500096];

__device__ __forceinline__ uint32_t smem_u32(const void* p) {
    uint32_t a;
    asm("{ .reg .u64 t; cvta.to.shared.u64 t, %1; cvt.u32.u64 %0, t; }"
        : "=r"(a) : "l"(p));
    return a;
}
__device__ __forceinline__ uint32_t pack_h2(__half a, __half b) {
    __half2 t = __halves2half2(a, b);
    return *reinterpret_cast<uint32_t*>(&t);
}
__device__ __forceinline__ void ldm_x4(uint32_t* r, uint32_t addr) {
    asm volatile("ldmatrix.sync.aligned.m8n8.x4.shared.b16 {%0,%1,%2,%3}, [%4];"
                 : "=r"(r[0]), "=r"(r[1]), "=r"(r[2]), "=r"(r[3]) : "r"(addr));
}
__device__ __forceinline__ void mma_f16(float* c, const uint32_t* a,
                                        const uint32_t* b) {
    asm volatile(
        "mma.sync.aligned.m16n8k16.row.col.f32.f16.f16.f32 "
        "{%0,%1,%2,%3}, {%4,%5,%6,%7}, {%8,%9}, {%0,%1,%2,%3};"
        : "+f"(c[0]), "+f"(c[1]), "+f"(c[2]), "+f"(c[3])
        : "r"(a[0]), "r"(a[1]), "r"(a[2]), "r"(a[3]), "r"(b[0]), "r"(b[1]));
}
__device__ __forceinline__ void cpa16(uint32_t ds, const void* src) {
    uint64_t gs;
    asm("cvta.to.global.u64 %0, %1;" : "=l"(gs) : "l"(src));
    asm volatile("cp.async.cg.shared.global [%0], [%1], 16;" :: "r"(ds), "l"(gs));
}
__device__ __forceinline__ void tmin(float& va, int& ia, float vb, int ib) {
    if (vb < va) { va = vb; ia = ib; }
}
// packed-key top-2 update: 3 IMNMX, no predicates
__device__ __forceinline__ void kins(uint32_t& m1, uint32_t& m2, uint32_t k) {
    uint32_t hi = umax(m1, k);
    m2 = umin(m2, hi);
    m1 = umin(m1, k);
}
__device__ __forceinline__ uint32_t mkkey(float v, uint32_t idx) {
    return (__float_as_uint(v + 512.f) & 0xFFFFFE00u) | idx;
}

// ---------------- prep ----------------
__global__ void prep_kernel(const float* __restrict__ cent)
{
    int r = blockIdx.x * blockDim.x + threadIdx.x;
    if (r >= KCENT) return;
    float s = 0.f;
#pragma unroll
    for (int d = 0; d < DIM; d++) {
        float c = cent[r * DIM + d];
        s = fmaf(c, c, s);
        float v = -2.f * c;
        __half h = __float2half_rn(v);
        g_bh[r][d] = h;
        g_bl[r][d] = __float2half_rn(v - __half2float(h));
    }
    g_c2[r] = s;
}

__global__ void prep2_kernel()
{
    __shared__ float sm[512];
    int t = threadIdx.x;
    sm[t] = g_c2[t];
    __syncthreads();
#pragma unroll
    for (int s = 256; s > 0; s >>= 1) {
        if (t < s) sm[t] = fmaxf(sm[t], sm[t + s]);
        __syncthreads();
    }
    if (t == 0) { g_maxn = 2.f * sqrtf(sm[0]); g_cnt = 0; }
}

// ---------------- pass 1: persistent hh screen, packed keys ----------------
extern __shared__ char smc[];

__global__ __launch_bounds__(THREADS, 1)
void pass1_kernel(const float* __restrict__ x, float* __restrict__ out,
                  int n, int ntiles)
{
    const int tid = threadIdx.x;
    const int lid = tid & 31;
    const int wid = tid >> 5;
    const int wm  = wid >> 1;
    const int wn  = wid & 1;
    const int lr  = lid >> 2;
    const int lc  = lid & 3;
    const uint32_t smb = smem_u32(smc);

    // ---- B (bh only): ONE cp.async group ----
#pragma unroll
    for (int j = 0; j < 8; j++) {
        int it = tid + j * THREADS;
        int r = it >> 3, q = it & 7;
        cpa16(smb + P1_SB + (uint32_t)r * 128u +
              (uint32_t)((q ^ (r & 7)) << 4),
              &g_bh[r][q * 8]);
    }
    asm volatile("cp.async.commit_group;");

    reinterpret_cast<float*>(smc + P1_SC2)[tid] = g_c2[tid];

    auto stageA = [&](int t, int par) {
        const int  r2 = tid >> 1, hf = tid & 1;
        const int  grow = t * TILE_M + r2;
        const bool vld = (grow < n);
        const float4* xr =
            reinterpret_cast<const float4*>(x + (size_t)grow * DIM) + hf * 8;
        const float4 z = make_float4(0.f, 0.f, 0.f, 0.f);
        const int rs = r2 & 7;
        float s2 = 0.f;
#pragma unroll
        for (int j = 0; j < 8; j++) {
            float4 c = vld ? xr[j] : z;
            s2 = fmaf(c.x, c.x, s2); s2 = fmaf(c.y, c.y, s2);
            s2 = fmaf(c.z, c.z, s2); s2 = fmaf(c.w, c.w, s2);
            __half h0 = __float2half_rn(c.x), h1 = __float2half_rn(c.y);
            __half h2 = __float2half_rn(c.z), h3 = __float2half_rn(c.w);
            const int colb = hf * 64 + j * 8;
            const int qidx = colb >> 4;
            const uint32_t off = (uint32_t)r2 * 128u +
                                 (uint32_t)((qidx ^ rs) << 4) +
                                 (uint32_t)(colb & 15);
            *reinterpret_cast<uint2*>(smc + P1_SA + off) =
                make_uint2(pack_h2(h0, h1), pack_h2(h2, h3));
        }
        reinterpret_cast<float*>(smc + P1_SXN)[par * 512 + hf * 256 + r2] = s2;
    };

    const int arow = ((lid >> 3) & 1) * 8 + (lid & 7);
    const int aq0  = lid >> 4;
    const int asw  = lid & 7;
    const int brow = ((lid >> 4) & 1) * 8 + (lid & 7);
    const int bq0  = (lid >> 3) & 1;
    const int bsw  = lid & 7;
    const uint32_t b_row_off = (uint32_t)(wn * 64 + brow) * 128u;

    int t = blockIdx.x;
    int par = 0;
    if (t < ntiles) stageA(t, 0);

    asm volatile("cp.async.wait_group 0;");
    __syncthreads();

    while (t < ntiles) {
        uint32_t AH[4][2][4];
#pragma unroll
        for (int s = 0; s < 4; s++) {
            const uint32_t aoff = (uint32_t)(((2 * s + aq0) ^ asw) << 4);
#pragma unroll
            for (int mt = 0; mt < 2; mt++)
                ldm_x4(AH[s][mt], smb + P1_SA +
                       (uint32_t)(wm * 32 + mt * 16 + arow) * 128u + aoff);
        }
        __syncthreads();

        // packed-key top-2 trackers
        uint32_t m1k[2][2] = {{0xFFFFFFFFu, 0xFFFFFFFFu},
                              {0xFFFFFFFFu, 0xFFFFFFFFu}};
        uint32_t m2k[2][2] = {{0xFFFFFFFFu, 0xFFFFFFFFu},
                              {0xFFFFFFFFu, 0xFFFFFFFFu}};

        auto compute = [&](int ch) {
            const uint32_t bb0 = smb + P1_SB + (uint32_t)ch * 16384u + b_row_off;
            const uint32_t idx0 = (uint32_t)(ch * CHN + wn * 64 + 2 * lc);
            const float* c2s = reinterpret_cast<const float*>(smc + P1_SC2) +
                               ch * CHN + wn * 64 + 2 * lc;
#pragma unroll
            for (int p = 0; p < 4; p++) {
                float acc[2][2][4];
                {
                    float2 cc0 = *reinterpret_cast<const float2*>(c2s + (2 * p) * 8);
                    float2 cc1 = *reinterpret_cast<const float2*>(c2s + (2 * p + 1) * 8);
#pragma unroll
                    for (int mt = 0; mt < 2; mt++) {
                        acc[mt][0][0] = cc0.x; acc[mt][0][1] = cc0.y;
                        acc[mt][0][2] = cc0.x; acc[mt][0][3] = cc0.y;
                        acc[mt][1][0] = cc1.x; acc[mt][1][1] = cc1.y;
                        acc[mt][1][2] = cc1.x; acc[mt][1][3] = cc1.y;
                    }
                }
#pragma unroll
                for (int s = 0; s < 4; s++) {
                    uint32_t bh4[4];
                    ldm_x4(bh4, bb0 + (uint32_t)(p * 16) * 128u +
                                (uint32_t)(((2 * s + bq0) ^ bsw) << 4));
                    mma_f16(acc[0][0], AH[s][0], bh4);
                    mma_f16(acc[0][1], AH[s][0], bh4 + 2);
                    mma_f16(acc[1][0], AH[s][1], bh4);
                    mma_f16(acc[1][1], AH[s][1], bh4 + 2);
                }
                const uint32_t ia = idx0 + (uint32_t)(2 * p) * 8u;
                const uint32_t ib = idx0 + (uint32_t)(2 * p + 1) * 8u;
#pragma unroll
                for (int mt = 0; mt < 2; mt++) {
#pragma unroll
                    for (int hc = 0; hc < 2; hc++) {
                        kins(m1k[mt][hc], m2k[mt][hc],
                             mkkey(acc[mt][0][2 * hc],     ia));
                        kins(m1k[mt][hc], m2k[mt][hc],
                             mkkey(acc[mt][0][2 * hc + 1], ia + 1));
                        kins(m1k[mt][hc], m2k[mt][hc],
                             mkkey(acc[mt][1][2 * hc],     ib));
                        kins(m1k[mt][hc], m2k[mt][hc],
                             mkkey(acc[mt][1][2 * hc + 1], ib + 1));
                    }
                }
            }
        };

        const int tnext = t + GRID1;
        compute(0);
        if (tnext < ntiles) stageA(tnext, par ^ 1);
        compute(1);
        compute(2);
        compute(3);

        // shuffle-merge packed keys over lc group (pure IMNMX)
#pragma unroll
        for (int mt = 0; mt < 2; mt++) {
#pragma unroll
            for (int hc = 0; hc < 2; hc++) {
#pragma unroll
                for (int d = 1; d <= 2; d <<= 1) {
                    uint32_t o1 = __shfl_xor_sync(0xFFFFFFFFu, m1k[mt][hc], d);
                    uint32_t o2 = __shfl_xor_sync(0xFFFFFFFFu, m2k[mt][hc], d);
                    uint32_t hi = umax(m1k[mt][hc], o1);
                    m1k[mt][hc] = umin(m1k[mt][hc], o1);
                    m2k[mt][hc] = umin(umin(m2k[mt][hc], o2), hi);
                }
            }
        }
        if (lc == 0) {
#pragma unroll
            for (int mt = 0; mt < 2; mt++) {
#pragma unroll
                for (int hc = 0; hc < 2; hc++) {
                    int rowl = wm * 32 + mt * 16 + hc * 8 + lr;
                    reinterpret_cast<uint32_t*>(smc + P1_RK1)[wn * 256 + rowl] =
                        m1k[mt][hc];
                    reinterpret_cast<uint32_t*>(smc + P1_RK2)[wn * 256 + rowl] =
                        m2k[mt][hc];
                }
            }
        }
        __syncthreads();

        if (tid < TILE_M) {
            uint32_t a1 = reinterpret_cast<uint32_t*>(smc + P1_RK1)[tid];
            uint32_t a2 = reinterpret_cast<uint32_t*>(smc + P1_RK2)[tid];
            uint32_t b1 = reinterpret_cast<uint32_t*>(smc + P1_RK1)[256 + tid];
            uint32_t b2 = reinterpret_cast<uint32_t*>(smc + P1_RK2)[256 + tid];
            uint32_t hi = umax(a1, b1);
            uint32_t m1 = umin(a1, b1);
            uint32_t m2 = umin(umin(a2, b2), hi);

            int grow = t * TILE_M + tid;
            if (grow < n) {
                int   i1  = (int)(m1 & 511u);
                float m1f = __uint_as_float(m1 & 0xFFFFFE00u) - 512.f;
                float m2f = __uint_as_float(m2 & 0xFFFFFE00u) - 512.f;
                float x2 =
                    reinterpret_cast<float*>(smc + P1_SXN)[par * 512 + tid] +
                    reinterpret_cast<float*>(smc + P1_SXN)[par * 512 + 256 + tid];
                // fp16 trunc bound + 2*key-mask error (<=0.0625 each) + slack
                float margin = 0.0019727f * sqrtf(x2) * g_maxn + 0.18f;
                out[grow] = (float)i1;
                if (!(m2f - m1f > margin)) {
                    int pos = atomicAdd(&g_cnt, 1);
                    g_list[pos] = grow;
                }
            }
        }
        __syncthreads();

        t = tnext;
        par ^= 1;
    }
}

// ---------------- pass 2: exact 3-term rescore ----------------
__global__ __launch_bounds__(THREADS, 1)
void pass2_kernel(const float* __restrict__ x, float* __restrict__ out)
{
    const int tid = threadIdx.x;
    const int lid = tid & 31;
    const int wid = tid >> 5;
    const int wm  = wid >> 1;
    const int wn  = wid & 1;
    const int lr  = lid >> 2;
    const int lc  = lid & 3;
    const uint32_t smb = smem_u32(smc);
    const int cnt = g_cnt;

#pragma unroll
    for (int j = 0; j < 16; j++) {
        int it  = tid + j * THREADS;
        int ch  = it >> 11;
        int var = (it >> 10) & 1;
        int rem = it & 1023;
        int r   = rem >> 3;
        int q   = rem & 7;
        const __half* src = var ? &g_bl[ch * CHN + r][q * 8]
                                : &g_bh[ch * CHN + r][q * 8];
        cpa16(smb + P2_SB + (uint32_t)ch * 32768u + (uint32_t)var * 16384u +
              (uint32_t)r * 128u + (uint32_t)((q ^ (r & 7)) << 4), src);
    }
    asm volatile("cp.async.commit_group;");
    reinterpret_cast<float*>(smc + P2_SC2)[tid] = g_c2[tid];

    const int arow = ((lid >> 3) & 1) * 8 + (lid & 7);
    const int aq0  = lid >> 4;
    const int asw  = lid & 7;
    const int brow = ((lid >> 4) & 1) * 8 + (lid & 7);
    const int bq0  = (lid >> 3) & 1;
    const int bsw  = lid & 7;
    const uint32_t b_row_off = (uint32_t)(wn * 64 + brow) * 128u;

    asm volatile("cp.async.wait_group 0;");
    __syncthreads();

    for (int base = blockIdx.x * TILE_M; base < cnt; base += P2GRID * TILE_M) {
        {
            const int  r2 = tid >> 1, hf = tid & 1;
            const int  j = base + r2;
            const bool vld = (j < cnt);
            const int  grow = vld ? g_list[j] : 0;
            const float4* xr =
                reinterpret_cast<const float4*>(x + (size_t)grow * DIM) + hf * 8;
            const float4 z = make_float4(0.f, 0.f, 0.f, 0.f);
            const int rs = r2 & 7;
#pragma unroll
            for (int jj = 0; jj < 8; jj++) {
                float4 c = vld ? xr[jj] : z;
                float a[4] = {c.x, c.y, c.z, c.w};
                __half h[4], l[4];
#pragma unroll
                for (int q = 0; q < 4; q++) {
                    h[q] = __float2half_rn(a[q]);
                    l[q] = __float2half_rn(a[q] - __half2float(h[q]));
                }
                const int colb = hf * 64 + jj * 8;
                const int qidx = colb >> 4;
                const uint32_t off = (uint32_t)r2 * 128u +
                                     (uint32_t)((qidx ^ rs) << 4) +
                                     (uint32_t)(colb & 15);
                *reinterpret_cast<uint2*>(smc + P2_SA + off) =
                    make_uint2(pack_h2(h[0], h[1]), pack_h2(h[2], h[3]));
                *reinterpret_cast<uint2*>(smc + P2_SA + 32768u + off) =
                    make_uint2(pack_h2(l[0], l[1]), pack_h2(l[2], l[3]));
            }
        }
        __syncthreads();

        uint32_t AH[4][2][4], AL[4][2][4];
#pragma unroll
        for (int s = 0; s < 4; s++) {
            const uint32_t aoff = (uint32_t)(((2 * s + aq0) ^ asw) << 4);
#pragma unroll
            for (int mt = 0; mt < 2; mt++) {
                const uint32_t rowb = (uint32_t)(wm * 32 + mt * 16 + arow) * 128u;
                ldm_x4(AH[s][mt], smb + P2_SA + rowb + aoff);
                ldm_x4(AL[s][mt], smb + P2_SA + 32768u + rowb + aoff);
            }
        }

        float bv[2][2] = {{3.4e38f, 3.4e38f}, {3.4e38f, 3.4e38f}};
        int   bi[2][2] = {{0, 0}, {0, 0}};

#pragma unroll
        for (int ch = 0; ch < NCH; ch++) {
            const uint32_t bb0 = smb + P2_SB + (uint32_t)ch * 32768u + b_row_off;
            const uint32_t bb1 = bb0 + 16384u;
            const int idx0 = ch * CHN + wn * 64 + 2 * lc;
            const float* c2s = reinterpret_cast<const float*>(smc + P2_SC2) +
                               ch * CHN + wn * 64 + 2 * lc;
#pragma unroll
            for (int p = 0; p < 4; p++) {
                float acc[2][2][4];
                {
                    float2 cc0 = *reinterpret_cast<const float2*>(c2s + (2 * p) * 8);
                    float2 cc1 = *reinterpret_cast<const float2*>(c2s + (2 * p + 1) * 8);
#pragma unroll
                    for (int mt = 0; mt < 2; mt++) {
                        acc[mt][0][0] = cc0.x; acc[mt][0][1] = cc0.y;
                        acc[mt][0][2] = cc0.x; acc[mt][0][3] = cc0.y;
                        acc[mt][1][0] = cc1.x; acc[mt][1][1] = cc1.y;
                        acc[mt][1][2] = cc1.x; acc[mt][1][3] = cc1.y;
                    }
                }
#pragma unroll
                for (int s = 0; s < 4; s++) {
                    uint32_t bh4[4], bl4[4];
                    const uint32_t ro = (uint32_t)(p * 16) * 128u +
                                        (uint32_t)(((2 * s + bq0) ^ bsw) << 4);
                    ldm_x4(bh4, bb0 + ro);
                    ldm_x4(bl4, bb1 + ro);
                    mma_f16(acc[0][0], AH[s][0], bh4);
                    mma_f16(acc[0][1], AH[s][0], bh4 + 2);
                    mma_f16(acc[1][0], AH[s][1], bh4);
                    mma_f16(acc[1][1], AH[s][1], bh4 + 2);
                    mma_f16(acc[0][0], AH[s][0], bl4);
                    mma_f16(acc[0][1], AH[s][0], bl4 + 2);
                    mma_f16(acc[1][0], AH[s][1], bl4);
                    mma_f16(acc[1][1], AH[s][1], bl4 + 2);
                    mma_f16(acc[0][0], AL[s][0], bh4);
                    mma_f16(acc[0][1], AL[s][0], bh4 + 2);
                    mma_f16(acc[1][0], AL[s][1], bh4);
                    mma_f16(acc[1][1], AL[s][1], bh4 + 2);
                }
#pragma unroll
                for (int mt = 0; mt < 2; mt++) {
#pragma unroll
                    for (int hc = 0; hc < 2; hc++) {
                        float v0 = acc[mt][0][2 * hc];
                        int   i0 = idx0 + (2 * p) * 8;
                        tmin(v0, i0, acc[mt][0][2 * hc + 1], i0 + 1);
                        float v1 = acc[mt][1][2 * hc];
                        int   i1 = idx0 + (2 * p + 1) * 8;
                        tmin(v1, i1, acc[mt][1][2 * hc + 1], i1 + 1);
                        tmin(v0, i0, v1, i1);
                        tmin(bv[mt][hc], bi[mt][hc], v0, i0);
                    }
                }
            }
        }

#pragma unroll
        for (int mt = 0; mt < 2; mt++) {
#pragma unroll
            for (int h = 0; h < 2; h++) {
#pragma unroll
                for (int d = 1; d <= 2; d <<= 1) {
                    float ov = __shfl_xor_sync(0xFFFFFFFFu, bv[mt][h], d);
                    int   oi = __shfl_xor_sync(0xFFFFFFFFu, bi[mt][h], d);
                    if (ov < bv[mt][h] || (ov == bv[mt][h] && oi < bi[mt][h])) {
                        bv[mt][h] = ov; bi[mt][h] = oi;
                    }
                }
            }
        }
        if (lc == 0) {
#pragma unroll
            for (int mt = 0; mt < 2; mt++) {
#pragma unroll
                for (int h = 0; h < 2; h++) {
                    int rowl = wm * 32 + mt * 16 + h * 8 + lr;
                    reinterpret_cast<float*>(smc + P2_RV)[wn * 256 + rowl] = bv[mt][h];
                    reinterpret_cast<int*>(smc + P2_RI)[wn * 256 + rowl]   = bi[mt][h];
                }
            }
        }
        __syncthreads();

        if (tid < TILE_M) {
            int j = base + tid;
            if (j < cnt) {
                float v0 = reinterpret_cast<float*>(smc + P2_RV)[tid];
                float v1 = reinterpret_cast<float*>(smc + P2_RV)[256 + tid];
                int   i0 = reinterpret_cast<int*>(smc + P2_RI)[tid];
                int   i1 = reinterpret_cast<int*>(smc + P2_RI)[256 + tid];
                int best = (v1 < v0 || (v1 == v0 && i1 < i0)) ? i1 : i0;
                out[g_list[j]] = (float)best;
            }
        }
        __syncthreads();
    }
}

// ---------------- launch ----------------
extern "C" void kernel_launch(void* const* d_in, const int* in_sizes, int n_in,
                              void* d_out, int out_size)
{
    const float* x = (const float*)d_in[0];
    const float* c = (const float*)d_in[1];
    float* out = (float*)d_out;

    const int n = in_sizes[0] / DIM;
    const int ntiles = (n + TILE_M - 1) / TILE_M;
    const int grid1 = (ntiles < GRID1) ? ntiles : GRID1;

    cudaFuncSetAttribute(pass1_kernel,
                         cudaFuncAttributeMaxDynamicSharedMemorySize, P1_SMEM);
    cudaFuncSetAttribute(pass2_kernel,
                         cudaFuncAttributeMaxDynamicSharedMemorySize, P2_SMEM);

    prep_kernel<<<4, 128>>>(c);
    prep2_kernel<<<1, 512>>>();
    pass1_kernel<<<grid1, THREADS, P1_SMEM>>>(x, out, n, ntiles);
    pass2_kernel<<<P2GRID, THREADS, P2_SMEM>>>(x, out);
}

// round 17
// speedup vs baseline: 1.0738x; 1.0738x over previous
#include <cuda_runtime.h>
#include <cuda_fp16.h>
#include <cstdint>

// KMeans labels, two-pass:
//  PASS 1 (persistent): hh-only fp16 MMA screen. B(hh) resident per SM.
//    Mainloop software-pipelined: iteration it issues MMAs into acc[it&1],
//    then runs the top-2 epilogue of iteration it-1 (acc latency hidden).
//    Gap > deterministic fp16 truncation margin -> argmin provably exact;
//    else point -> rescue list.
//  PASS 2: exact 3-term (hh+hl+lh) fp16-split MMA rescore of listed points.
// Margin: |true-hh| <= 2^-10*1.01*||x||*max||2c|| + slack.

#define DIM      64
#define KCENT    512
#define TILE_M   256
#define CHN      128
#define NCH      4
#define THREADS  512
#define GRID1    148
#define P2GRID   148

// ---- pass1 smem ----
#define P1_SA   0u
#define P1_SB   32768u
#define P1_SC2  98304u
#define P1_SXN  100352u
#define P1_RV1  104448u
#define P1_RI1  106496u
#define P1_RV2  108544u
#define P1_SMEM 110592u

// ---- pass2 smem ----
#define P2_SA   0u
#define P2_SB   65536u
#define P2_SC2  196608u
#define P2_RV   198656u
#define P2_RI   200704u
#define P2_SMEM 202752u

__device__ __align__(16) __half g_bh[KCENT][DIM];   // rn16(-2c)
__device__ __align__(16) __half g_bl[KCENT][DIM];   // rn16(-2c - h)
__device__ __align__(16) float  g_c2[KCENT];
__device__ float g_maxn;
__device__ int   g_cnt;
__device__ int   g_list[500096];

__device__ __forceinline__ uint32_t smem_u32(const void* p) {
    uint32_t a;
    asm("{ .reg .u64 t; cvta.to.shared.u64 t, %1; cvt.u32.u64 %0, t; }"
        : "=r"(a) : "l"(p));
    return a;
}
__device__ __forceinline__ uint32_t pack_h2(__half a, __half b) {
    __half2 t = __halves2half2(a, b);
    return *reinterpret_cast<uint32_t*>(&t);
}
__device__ __forceinline__ void ldm_x4(uint32_t* r, uint32_t addr) {
    asm volatile("ldmatrix.sync.aligned.m8n8.x4.shared.b16 {%0,%1,%2,%3}, [%4];"
                 : "=r"(r[0]), "=r"(r[1]), "=r"(r[2]), "=r"(r[3]) : "r"(addr));
}
__device__ __forceinline__ void mma_f16(float* c, const uint32_t* a,
                                        const uint32_t* b) {
    asm volatile(
        "mma.sync.aligned.m16n8k16.row.col.f32.f16.f16.f32 "
        "{%0,%1,%2,%3}, {%4,%5,%6,%7}, {%8,%9}, {%0,%1,%2,%3};"
        : "+f"(c[0]), "+f"(c[1]), "+f"(c[2]), "+f"(c[3])
        : "r"(a[0]), "r"(a[1]), "r"(a[2]), "r"(a[3]), "r"(b[0]), "r"(b[1]));
}
__device__ __forceinline__ void cpa16(uint32_t ds, const void* src) {
    uint64_t gs;
    asm("cvta.to.global.u64 %0, %1;" : "=l"(gs) : "l"(src));
    asm volatile("cp.async.cg.shared.global [%0], [%1], 16;" :: "r"(ds), "l"(gs));
}
__device__ __forceinline__ void tmin(float& va, int& ia, float vb, int ib) {
    if (vb < va) { va = vb; ia = ib; }
}

// ---------------- prep ----------------
__global__ void prep_kernel(const float* __restrict__ cent)
{
    int r = blockIdx.x * blockDim.x + threadIdx.x;
    if (r >= KCENT) return;
    float s = 0.f;
#pragma unroll
    for (int d = 0; d < DIM; d++) {
        float c = cent[r * DIM + d];
        s = fmaf(c, c, s);
        float v = -2.f * c;
        __half h = __float2half_rn(v);
        g_bh[r][d] = h;
        g_bl[r][d] = __float2half_rn(v - __half2float(h));
    }
    g_c2[r] = s;
}

__global__ void prep2_kernel()
{
    __shared__ float sm[512];
    int t = threadIdx.x;
    sm[t] = g_c2[t];
    __syncthreads();
#pragma unroll
    for (int s = 256; s > 0; s >>= 1) {
        if (t < s) sm[t] = fmaxf(sm[t], sm[t + s]);
        __syncthreads();
    }
    if (t == 0) { g_maxn = 2.f * sqrtf(sm[0]); g_cnt = 0; }
}

// ---------------- pass 1: persistent hh screen, pipelined epilogue ----------------
extern __shared__ char smc[];

__global__ __launch_bounds__(THREADS, 1)
void pass1_kernel(const float* __restrict__ x, float* __restrict__ out,
                  int n, int ntiles)
{
    const int tid = threadIdx.x;
    const int lid = tid & 31;
    const int wid = tid >> 5;
    const int wm  = wid >> 1;
    const int wn  = wid & 1;
    const int lr  = lid >> 2;
    const int lc  = lid & 3;
    const uint32_t smb = smem_u32(smc);

    // ---- B (bh only): ONE cp.async group ----
#pragma unroll
    for (int j = 0; j < 8; j++) {
        int it = tid + j * THREADS;
        int r = it >> 3, q = it & 7;
        cpa16(smb + P1_SB + (uint32_t)r * 128u +
              (uint32_t)((q ^ (r & 7)) << 4),
              &g_bh[r][q * 8]);
    }
    asm volatile("cp.async.commit_group;");

    reinterpret_cast<float*>(smc + P1_SC2)[tid] = g_c2[tid];

    auto stageA = [&](int t, int par) {
        const int  r2 = tid >> 1, hf = tid & 1;
        const int  grow = t * TILE_M + r2;
        const bool vld = (grow < n);
        const float4* xr =
            reinterpret_cast<const float4*>(x + (size_t)grow * DIM) + hf * 8;
        const float4 z = make_float4(0.f, 0.f, 0.f, 0.f);
        const int rs = r2 & 7;
        float s2 = 0.f;
#pragma unroll
        for (int j = 0; j < 8; j++) {
            float4 c = vld ? xr[j] : z;
            s2 = fmaf(c.x, c.x, s2); s2 = fmaf(c.y, c.y, s2);
            s2 = fmaf(c.z, c.z, s2); s2 = fmaf(c.w, c.w, s2);
            __half h0 = __float2half_rn(c.x), h1 = __float2half_rn(c.y);
            __half h2 = __float2half_rn(c.z), h3 = __float2half_rn(c.w);
            const int colb = hf * 64 + j * 8;
            const int qidx = colb >> 4;
            const uint32_t off = (uint32_t)r2 * 128u +
                                 (uint32_t)((qidx ^ rs) << 4) +
                                 (uint32_t)(colb & 15);
            *reinterpret_cast<uint2*>(smc + P1_SA + off) =
                make_uint2(pack_h2(h0, h1), pack_h2(h2, h3));
        }
        reinterpret_cast<float*>(smc + P1_SXN)[par * 512 + hf * 256 + r2] = s2;
    };

    const int arow = ((lid >> 3) & 1) * 8 + (lid & 7);
    const int aq0  = lid >> 4;
    const int asw  = lid & 7;
    const int brow = ((lid >> 4) & 1) * 8 + (lid & 7);
    const int bq0  = (lid >> 3) & 1;
    const int bsw  = lid & 7;
    const uint32_t b_row_off = (uint32_t)(wn * 64 + brow) * 128u;

    int t = blockIdx.x;
    int par = 0;
    if (t < ntiles) stageA(t, 0);

    asm volatile("cp.async.wait_group 0;");
    __syncthreads();

    while (t < ntiles) {
        uint32_t AH[4][2][4];
#pragma unroll
        for (int s = 0; s < 4; s++) {
            const uint32_t aoff = (uint32_t)(((2 * s + aq0) ^ asw) << 4);
#pragma unroll
            for (int mt = 0; mt < 2; mt++)
                ldm_x4(AH[s][mt], smb + P1_SA +
                       (uint32_t)(wm * 32 + mt * 16 + arow) * 128u + aoff);
        }
        __syncthreads();

        float m1v[2][2] = {{3.4e38f, 3.4e38f}, {3.4e38f, 3.4e38f}};
        float m2v[2][2] = {{3.4e38f, 3.4e38f}, {3.4e38f, 3.4e38f}};
        int   i1v[2][2] = {{0, 0}, {0, 0}};

        auto ins = [&](int mt, int hc, float v, int i) {
            if (v < m1v[mt][hc]) {
                m2v[mt][hc] = m1v[mt][hc];
                m1v[mt][hc] = v; i1v[mt][hc] = i;
            } else {
                m2v[mt][hc] = fminf(m2v[mt][hc], v);
            }
        };

        // acc double buffer + per-buffer base index
        float acc[2][2][2][4];          // [buf][mt][nt][4]
        int   pbase[2];

        // epilogue of one buffered iteration (16 candidates via ins())
        auto epi = [&](int buf) {
            const int ia = pbase[buf];
            const int ib = ia + 8;
#pragma unroll
            for (int mt = 0; mt < 2; mt++) {
#pragma unroll
                for (int hc = 0; hc < 2; hc++) {
                    ins(mt, hc, acc[buf][mt][0][2 * hc],     ia);
                    ins(mt, hc, acc[buf][mt][0][2 * hc + 1], ia + 1);
                    ins(mt, hc, acc[buf][mt][1][2 * hc],     ib);
                    ins(mt, hc, acc[buf][mt][1][2 * hc + 1], ib + 1);
                }
            }
        };

        const int tnext = t + GRID1;

        // ---- flattened pipelined mainloop: 16 (ch,p) iterations ----
#pragma unroll
        for (int it = 0; it < 16; it++) {
            const int ch  = it >> 2;
            const int p   = it & 3;
            const int cur = it & 1;
            const uint32_t bb0 = smb + P1_SB + (uint32_t)ch * 16384u + b_row_off;
            const float* c2s = reinterpret_cast<const float*>(smc + P1_SC2) +
                               ch * CHN + wn * 64 + 2 * lc;

            pbase[cur] = ch * CHN + wn * 64 + 2 * lc + (2 * p) * 8;
            {
                float2 cc0 = *reinterpret_cast<const float2*>(c2s + (2 * p) * 8);
                float2 cc1 = *reinterpret_cast<const float2*>(c2s + (2 * p + 1) * 8);
#pragma unroll
                for (int mt = 0; mt < 2; mt++) {
                    acc[cur][mt][0][0] = cc0.x; acc[cur][mt][0][1] = cc0.y;
                    acc[cur][mt][0][2] = cc0.x; acc[cur][mt][0][3] = cc0.y;
                    acc[cur][mt][1][0] = cc1.x; acc[cur][mt][1][1] = cc1.y;
                    acc[cur][mt][1][2] = cc1.x; acc[cur][mt][1][3] = cc1.y;
                }
            }
#pragma unroll
            for (int s = 0; s < 4; s++) {
                uint32_t bh4[4];
                ldm_x4(bh4, bb0 + (uint32_t)(p * 16) * 128u +
                            (uint32_t)(((2 * s + bq0) ^ bsw) << 4));
                mma_f16(acc[cur][0][0], AH[s][0], bh4);
                mma_f16(acc[cur][0][1], AH[s][0], bh4 + 2);
                mma_f16(acc[cur][1][0], AH[s][1], bh4);
                mma_f16(acc[cur][1][1], AH[s][1], bh4 + 2);
            }
            // epilogue of the PREVIOUS iteration (latency hidden by the
            // 16 MMAs just issued)
            if (it > 0) epi(cur ^ 1);
            // stage next tile's A once chunk 0 is in flight
            if (it == 3 && tnext < ntiles) stageA(tnext, par ^ 1);
        }
        epi(1);   // iteration 15 lives in buffer 1

        // ---- shuffle-merge triplets over lc group ----
#pragma unroll
        for (int mt = 0; mt < 2; mt++) {
#pragma unroll
            for (int hc = 0; hc < 2; hc++) {
#pragma unroll
                for (int d = 1; d <= 2; d <<= 1) {
                    float om1 = __shfl_xor_sync(0xFFFFFFFFu, m1v[mt][hc], d);
                    int   oi1 = __shfl_xor_sync(0xFFFFFFFFu, i1v[mt][hc], d);
                    float om2 = __shfl_xor_sync(0xFFFFFFFFu, m2v[mt][hc], d);
                    bool take = (om1 < m1v[mt][hc]) ||
                                (om1 == m1v[mt][hc] && oi1 < i1v[mt][hc]);
                    float losm = take ? m1v[mt][hc] : om1;
                    if (take) { m1v[mt][hc] = om1; i1v[mt][hc] = oi1; }
                    m2v[mt][hc] = fminf(fminf(m2v[mt][hc], om2), losm);
                }
            }
        }
        if (lc == 0) {
#pragma unroll
            for (int mt = 0; mt < 2; mt++) {
#pragma unroll
                for (int hc = 0; hc < 2; hc++) {
                    int rowl = wm * 32 + mt * 16 + hc * 8 + lr;
                    reinterpret_cast<float*>(smc + P1_RV1)[wn * 256 + rowl] = m1v[mt][hc];
                    reinterpret_cast<int*>(smc + P1_RI1)[wn * 256 + rowl]   = i1v[mt][hc];
                    reinterpret_cast<float*>(smc + P1_RV2)[wn * 256 + rowl] = m2v[mt][hc];
                }
            }
        }
        __syncthreads();

        if (tid < TILE_M) {
            float a1 = reinterpret_cast<float*>(smc + P1_RV1)[tid];
            int   ai = reinterpret_cast<int*>(smc + P1_RI1)[tid];
            float a2 = reinterpret_cast<float*>(smc + P1_RV2)[tid];
            float b1 = reinterpret_cast<float*>(smc + P1_RV1)[256 + tid];
            int   bi = reinterpret_cast<int*>(smc + P1_RI1)[256 + tid];
            float b2 = reinterpret_cast<float*>(smc + P1_RV2)[256 + tid];
            bool take = (b1 < a1) || (b1 == a1 && bi < ai);
            float losm = take ? a1 : b1;
            float m1 = take ? b1 : a1;
            int   i1 = take ? bi : ai;
            float m2 = fminf(fminf(a2, b2), losm);

            int grow = t * TILE_M + tid;
            if (grow < n) {
                float x2 =
                    reinterpret_cast<float*>(smc + P1_SXN)[par * 512 + tid] +
                    reinterpret_cast<float*>(smc + P1_SXN)[par * 512 + 256 + tid];
                float margin = 0.0019727f * sqrtf(x2) * g_maxn + 0.05f;
                out[grow] = (float)i1;
                if (!(m2 - m1 > margin)) {
                    int pos = atomicAdd(&g_cnt, 1);
                    g_list[pos] = grow;
                }
            }
        }
        __syncthreads();

        t = tnext;
        par ^= 1;
    }
}

// ---------------- pass 2: exact 3-term rescore ----------------
__global__ __launch_bounds__(THREADS, 1)
void pass2_kernel(const float* __restrict__ x, float* __restrict__ out)
{
    const int tid = threadIdx.x;
    const int lid = tid & 31;
    const int wid = tid >> 5;
    const int wm  = wid >> 1;
    const int wn  = wid & 1;
    const int lr  = lid >> 2;
    const int lc  = lid & 3;
    const uint32_t smb = smem_u32(smc);
    const int cnt = g_cnt;

#pragma unroll
    for (int j = 0; j < 16; j++) {
        int it  = tid + j * THREADS;
        int ch  = it >> 11;
        int var = (it >> 10) & 1;
        int rem = it & 1023;
        int r   = rem >> 3;
        int q   = rem & 7;
        const __half* src = var ? &g_bl[ch * CHN + r][q * 8]
                                : &g_bh[ch * CHN + r][q * 8];
        cpa16(smb + P2_SB + (uint32_t)ch * 32768u + (uint32_t)var * 16384u +
              (uint32_t)r * 128u + (uint32_t)((q ^ (r & 7)) << 4), src);
    }
    asm volatile("cp.async.commit_group;");
    reinterpret_cast<float*>(smc + P2_SC2)[tid] = g_c2[tid];

    const int arow = ((lid >> 3) & 1) * 8 + (lid & 7);
    const int aq0  = lid >> 4;
    const int asw  = lid & 7;
    const int brow = ((lid >> 4) & 1) * 8 + (lid & 7);
    const int bq0  = (lid >> 3) & 1;
    const int bsw  = lid & 7;
    const uint32_t b_row_off = (uint32_t)(wn * 64 + brow) * 128u;

    asm volatile("cp.async.wait_group 0;");
    __syncthreads();

    for (int base = blockIdx.x * TILE_M; base < cnt; base += P2GRID * TILE_M) {
        {
            const int  r2 = tid >> 1, hf = tid & 1;
            const int  j = base + r2;
            const bool vld = (j < cnt);
            const int  grow = vld ? g_list[j] : 0;
            const float4* xr =
                reinterpret_cast<const float4*>(x + (size_t)grow * DIM) + hf * 8;
            const float4 z = make_float4(0.f, 0.f, 0.f, 0.f);
            const int rs = r2 & 7;
#pragma unroll
            for (int jj = 0; jj < 8; jj++) {
                float4 c = vld ? xr[jj] : z;
                float a[4] = {c.x, c.y, c.z, c.w};
                __half h[4], l[4];
#pragma unroll
                for (int q = 0; q < 4; q++) {
                    h[q] = __float2half_rn(a[q]);
                    l[q] = __float2half_rn(a[q] - __half2float(h[q]));
                }
                const int colb = hf * 64 + jj * 8;
                const int qidx = colb >> 4;
                const uint32_t off = (uint32_t)r2 * 128u +
                                     (uint32_t)((qidx ^ rs) << 4) +
                                     (uint32_t)(colb & 15);
                *reinterpret_cast<uint2*>(smc + P2_SA + off) =
                    make_uint2(pack_h2(h[0], h[1]), pack_h2(h[2], h[3]));
                *reinterpret_cast<uint2*>(smc + P2_SA + 32768u + off) =
                    make_uint2(pack_h2(l[0], l[1]), pack_h2(l[2], l[3]));
            }
        }
        __syncthreads();

        uint32_t AH[4][2][4], AL[4][2][4];
#pragma unroll
        for (int s = 0; s < 4; s++) {
            const uint32_t aoff = (uint32_t)(((2 * s + aq0) ^ asw) << 4);
#pragma unroll
            for (int mt = 0; mt < 2; mt++) {
                const uint32_t rowb = (uint32_t)(wm * 32 + mt * 16 + arow) * 128u;
                ldm_x4(AH[s][mt], smb + P2_SA + rowb + aoff);
                ldm_x4(AL[s][mt], smb + P2_SA + 32768u + rowb + aoff);
            }
        }

        float bv[2][2] = {{3.4e38f, 3.4e38f}, {3.4e38f, 3.4e38f}};
        int   bi[2][2] = {{0, 0}, {0, 0}};

#pragma unroll
        for (int ch = 0; ch < NCH; ch++) {
            const uint32_t bb0 = smb + P2_SB + (uint32_t)ch * 32768u + b_row_off;
            const uint32_t bb1 = bb0 + 16384u;
            const int idx0 = ch * CHN + wn * 64 + 2 * lc;
            const float* c2s = reinterpret_cast<const float*>(smc + P2_SC2) +
                               ch * CHN + wn * 64 + 2 * lc;
#pragma unroll
            for (int p = 0; p < 4; p++) {
                float acc[2][2][4];
                {
                    float2 cc0 = *reinterpret_cast<const float2*>(c2s + (2 * p) * 8);
                    float2 cc1 = *reinterpret_cast<const float2*>(c2s + (2 * p + 1) * 8);
#pragma unroll
                    for (int mt = 0; mt < 2; mt++) {
                        acc[mt][0][0] = cc0.x; acc[mt][0][1] = cc0.y;
                        acc[mt][0][2] = cc0.x; acc[mt][0][3] = cc0.y;
                        acc[mt][1][0] = cc1.x; acc[mt][1][1] = cc1.y;
                        acc[mt][1][2] = cc1.x; acc[mt][1][3] = cc1.y;
                    }
                }
#pragma unroll
                for (int s = 0; s < 4; s++) {
                    uint32_t bh4[4], bl4[4];
                    const uint32_t ro = (uint32_t)(p * 16) * 128u +
                                        (uint32_t)(((2 * s + bq0) ^ bsw) << 4);
                    ldm_x4(bh4, bb0 + ro);
                    ldm_x4(bl4, bb1 + ro);
                    mma_f16(acc[0][0], AH[s][0], bh4);
                    mma_f16(acc[0][1], AH[s][0], bh4 + 2);
                    mma_f16(acc[1][0], AH[s][1], bh4);
                    mma_f16(acc[1][1], AH[s][1], bh4 + 2);
                    mma_f16(acc[0][0], AH[s][0], bl4);
                    mma_f16(acc[0][1], AH[s][0], bl4 + 2);
                    mma_f16(acc[1][0], AH[s][1], bl4);
                    mma_f16(acc[1][1], AH[s][1], bl4 + 2);
                    mma_f16(acc[0][0], AL[s][0], bh4);
                    mma_f16(acc[0][1], AL[s][0], bh4 + 2);
                    mma_f16(acc[1][0], AL[s][1], bh4);
                    mma_f16(acc[1][1], AL[s][1], bh4 + 2);
                }
#pragma unroll
                for (int mt = 0; mt < 2; mt++) {
#pragma unroll
                    for (int hc = 0; hc < 2; hc++) {
                        float v0 = acc[mt][0][2 * hc];
                        int   i0 = idx0 + (2 * p) * 8;
                        tmin(v0, i0, acc[mt][0][2 * hc + 1], i0 + 1);
                        float v1 = acc[mt][1][2 * hc];
                        int   i1 = idx0 + (2 * p + 1) * 8;
                        tmin(v1, i1, acc[mt][1][2 * hc + 1], i1 + 1);
                        tmin(v0, i0, v1, i1);
                        tmin(bv[mt][hc], bi[mt][hc], v0, i0);
                    }
                }
            }
        }

#pragma unroll
        for (int mt = 0; mt < 2; mt++) {
#pragma unroll
            for (int h = 0; h < 2; h++) {
#pragma unroll
                for (int d = 1; d <= 2; d <<= 1) {
                    float ov = __shfl_xor_sync(0xFFFFFFFFu, bv[mt][h], d);
                    int   oi = __shfl_xor_sync(0xFFFFFFFFu, bi[mt][h], d);
                    if (ov < bv[mt][h] || (ov == bv[mt][h] && oi < bi[mt][h])) {
                        bv[mt][h] = ov; bi[mt][h] = oi;
                    }
                }
            }
        }
        if (lc == 0) {
#pragma unroll
            for (int mt = 0; mt < 2; mt++) {
#pragma unroll
                for (int h = 0; h < 2; h++) {
                    int rowl = wm * 32 + mt * 16 + h * 8 + lr;
                    reinterpret_cast<float*>(smc + P2_RV)[wn * 256 + rowl] = bv[mt][h];
                    reinterpret_cast<int*>(smc + P2_RI)[wn * 256 + rowl]   = bi[mt][h];
                }
            }
        }
        __syncthreads();

        if (tid < TILE_M) {
            int j = base + tid;
            if (j < cnt) {
                float v0 = reinterpret_cast<float*>(smc + P2_RV)[tid];
                float v1 = reinterpret_cast<float*>(smc + P2_RV)[256 + tid];
                int   i0 = reinterpret_cast<int*>(smc + P2_RI)[tid];
                int   i1 = reinterpret_cast<int*>(smc + P2_RI)[256 + tid];
                int best = (v1 < v0 || (v1 == v0 && i1 < i0)) ? i1 : i0;
                out[g_list[j]] = (float)best;
            }
        }
        __syncthreads();
    }
}

// ---------------- launch ----------------
extern "C" void kernel_launch(void* const* d_in, const int* in_sizes, int n_in,
                              void* d_out, int out_size)
{
    const float* x = (const float*)d_in[0];
    const float* c = (const float*)d_in[1];
    float* out = (float*)d_out;

    const int n = in_sizes[0] / DIM;
    const int ntiles = (n + TILE_M - 1) / TILE_M;
    const int grid1 = (ntiles < GRID1) ? ntiles : GRID1;

    cudaFuncSetAttribute(pass1_kernel,
                         cudaFuncAttributeMaxDynamicSharedMemorySize, P1_SMEM);
    cudaFuncSetAttribute(pass2_kernel,
                         cudaFuncAttributeMaxDynamicSharedMemorySize, P2_SMEM);

    prep_kernel<<<4, 128>>>(c);
    prep2_kernel<<<1, 512>>>();
    pass1_kernel<<<grid1, THREADS, P1_SMEM>>>(x, out, n, ntiles);
    pass2_kernel<<<P2GRID, THREADS, P2_SMEM>>>(x, out);
}